// round 17
// speedup vs baseline: 10.8885x; 1.0799x over previous
#include <cuda_runtime.h>
#include <cuda_bf16.h>
#include <math.h>

// ============================================================================
// BUTD caption decoder, round 17.
//  - R16 fix: gi1ctot GEMM (reads gi1mean via FLAG_DMOD) raced with the
//    gi1mean-producing GEMM inside one merged launch. Split: mma_multi<5>
//    (independent) then mma_multi<1> (gi1ctot, depends on gi1mean).
//  - keeps R16's packed vectorized conversions + fused add_mean epilogue.
// ============================================================================

#define B_      128
#define NOBJ_   36
#define VDIM_   2048
#define HID_    1024
#define EMBED_  1024
#define NTOK_   15000
#define MAXLEN_ 20
#define TSTEPS_ 19
#define H3_     3072
#define XW_     2048

typedef unsigned int u32;
typedef unsigned short u16;

// ---------------- device scratch ---------------------------------------------
__device__ float g_Xbig[(TSTEPS_ + 1) * B_ * XW_];
__device__ float g_logits[(size_t)TSTEPS_ * B_ * NTOK_];
__device__ float g_h1[B_ * HID_];
__device__ float g_gp[B_ * H3_];
__device__ float g_gq[B_ * H3_];
__device__ float g_gs[B_ * H3_];
__device__ float g_q  [B_ * HID_];
__device__ float g_q2 [B_ * HID_];
__device__ float g_gi2h [B_ * H3_];
__device__ float g_gi2h2[B_ * H3_];
__device__ float g_gi1ctot[TSTEPS_ * B_ * H3_];
__device__ float g_gi1mean[B_ * H3_];
__device__ float g_vproj[B_ * NOBJ_ * HID_];
__device__ float g_alpha[B_ * TSTEPS_ * NOBJ_];
__device__ float g_WfcT [HID_ * HID_];
__device__ float g_WqfF [HID_ * HID_];
__device__ float g_Wih2fF[H3_ * HID_];
__device__ float g_bqf  [HID_];
__device__ float g_bih2f[H3_];
__device__ int   g_sortid[B_];
__device__ int   g_rowmap[TSTEPS_ * B_];
__device__ int   g_rowcnt[1];
__device__ unsigned g_bar_cnt;

// bf16 buffers
__device__ __align__(16) u16 g_h1b16[B_ * HID_];
__device__ __align__(16) u16 g_Xb16[(TSTEPS_ + 1) * B_ * HID_];
__device__ __align__(16) u16 g_histb16[TSTEPS_ * B_ * HID_];
__device__ __align__(16) u16 g_capb16[TSTEPS_ * B_ * EMBED_];
__device__ __align__(16) u16 g_vb16[B_ * NOBJ_ * VDIM_];
__device__ __align__(16) u16 g_vmeanb[B_ * VDIM_];
__device__ __align__(16) u16 g_Wq_b16[HID_ * HID_];
__device__ __align__(16) u16 g_Wih1_b [H3_ * 4096];
__device__ __align__(16) u16 g_Whh1_b [H3_ * HID_];
__device__ __align__(16) u16 g_Whh2_b [H3_ * HID_];
__device__ __align__(16) u16 g_Wih2_b [H3_ * H3_ ];
__device__ __align__(16) u16 g_Wqf_b  [HID_ * HID_];
__device__ __align__(16) u16 g_Wih2f_b[H3_ * HID_];
__device__ __align__(16) u16 g_WfcT_b [HID_ * HID_];
__device__ __align__(16) u16 g_Wv_b   [HID_ * VDIM_];
__device__ __align__(16) u16 g_Wfc2_b [NTOK_ * HID_];
__device__ __align__(16) u16 g_vW2b   [(size_t)B_ * NOBJ_ * H3_];

#define FLAG_RELU 2
#define FLAG_BF16 4
#define FLAG_DMOD 8

__device__ __forceinline__ void mma16(float* c, const u32* a, u32 b0, u32 b1) {
    asm volatile(
        "mma.sync.aligned.m16n8k16.row.col.f32.bf16.bf16.f32 "
        "{%0,%1,%2,%3}, {%4,%5,%6,%7}, {%8,%9}, {%0,%1,%2,%3};"
        : "+f"(c[0]), "+f"(c[1]), "+f"(c[2]), "+f"(c[3])
        : "r"(a[0]), "r"(a[1]), "r"(a[2]), "r"(a[3]), "r"(b0), "r"(b1));
}
__device__ __forceinline__ u32 pack_bf2(float lo, float hi) {
    u32 r; asm("cvt.rn.bf16x2.f32 %0, %1, %2;" : "=r"(r) : "f"(hi), "f"(lo));
    return r;
}
__device__ __forceinline__ u32 smem_u32(const void* p) {
    u32 a;
    asm("{ .reg .u64 t; cvta.to.shared.u64 t, %1; cvt.u32.u64 %0, t; }"
        : "=r"(a) : "l"(p));
    return a;
}
__device__ __forceinline__ void ldsm4(u32& r0, u32& r1, u32& r2, u32& r3, u32 addr) {
    asm volatile("ldmatrix.sync.aligned.m8n8.x4.shared.b16 {%0,%1,%2,%3}, [%4];"
        : "=r"(r0), "=r"(r1), "=r"(r2), "=r"(r3) : "r"(addr));
}
__device__ __forceinline__ void cp16(u32 dst, const void* src) {
    asm volatile("cp.async.ca.shared.global [%0], [%1], 16;"
        :: "r"(dst), "l"(src) : "memory");
}
__device__ __forceinline__ void cp16z(u32 dst, const void* src, u32 nbytes) {
    asm volatile("cp.async.ca.shared.global [%0], [%1], 16, %2;"
        :: "r"(dst), "l"(src), "r"(nbytes) : "memory");
}
#define CP_COMMIT() asm volatile("cp.async.commit_group;" ::: "memory")
#define CP_WAIT1()  asm volatile("cp.async.wait_group 1;" ::: "memory")

// ---------------- monotonic grid barrier (RED arrival) -------------------------
__device__ __forceinline__ void grid_bar(unsigned target) {
    __syncthreads();
    if (threadIdx.x == 0) {
        __threadfence();
        atomicAdd(&g_bar_cnt, 1u);
        while (*(volatile unsigned*)&g_bar_cnt < target) {}
        __threadfence();
    }
    __syncthreads();
}

// BK=64: rows of 64 bf16, smem pitch 36 u32 (144 B)
#define RP      36
#define A_ST    (128 * RP)
#define BL_ST   (64 * RP)
#define B2_ST   (128 * RP)
#define A_ST4   (A_ST * 4)
#define BL_ST4  (BL_ST * 4)
#define B2_ST4  (B2_ST * 4)
#define LOOP_SMEM ((3 * A_ST + 3 * BL_ST) * 4)
#define MM_SMEM   ((3 * A_ST + 3 * B2_ST) * 4)

struct FragAddr { u32 a[2]; u32 b[2]; };
__device__ __forceinline__ FragAddr frag_setup(
    const void* As, const void* Bs, int wm, int wn, int lane)
{
    FragAddr f;
    const u32 AsB = smem_u32(As);
    const u32 BsB = smem_u32(Bs);
    const int rowA = wm + (lane & 7) + ((lane >> 3) & 1) * 8;
    const int kwA  = ((lane >> 4) & 1) * 4;
    const int rowB = wn + (lane & 7) + ((lane >> 4) & 1) * 8;
    const int kwB  = ((lane >> 3) & 1) * 4;
    #pragma unroll
    for (int mt = 0; mt < 2; mt++)
        f.a[mt] = AsB + (u32)(((rowA + mt * 16) * RP + kwA) * 4);
    #pragma unroll
    for (int np = 0; np < 2; np++)
        f.b[np] = BsB + (u32)(((rowB + np * 16) * RP + kwB) * 4);
    return f;
}

__device__ __forceinline__ void mma_slab64(
    float acc[2][4][4], const FragAddr& f, u32 bufA, u32 bufB)
{
    #pragma unroll
    for (int ks = 0; ks < 4; ks++) {
        const u32 ko = ks * 32;
        u32 a0[4], a1[4], bA[4], bB[4];
        ldsm4(a0[0], a0[1], a0[2], a0[3], f.a[0] + bufA + ko);
        ldsm4(a1[0], a1[1], a1[2], a1[3], f.a[1] + bufA + ko);
        ldsm4(bA[0], bA[1], bA[2], bA[3], f.b[0] + bufB + ko);
        ldsm4(bB[0], bB[1], bB[2], bB[3], f.b[1] + bufB + ko);
        mma16(acc[0][0], a0, bA[0], bA[1]);
        mma16(acc[1][0], a1, bA[0], bA[1]);
        mma16(acc[0][1], a0, bA[2], bA[3]);
        mma16(acc[1][1], a1, bA[2], bA[3]);
        mma16(acc[0][2], a0, bB[0], bB[1]);
        mma16(acc[1][2], a1, bB[0], bB[1]);
        mma16(acc[0][3], a0, bB[2], bB[3]);
        mma16(acc[1][3], a1, bB[2], bB[3]);
    }
}

// ---------------- loop GEMM tile (128x64, BK=64, 3-stage cp.async) -------------
__device__ __forceinline__ void gemm_tile(
    const u16* __restrict__ A, int lda,
    const u16* __restrict__ W, int ldw,
    float* __restrict__ C, int ldc,
    const float* __restrict__ bias, const float* __restrict__ D,
    int bn, int K,
    u32* As, u32* Bs)
{
    const int tid = threadIdx.x;
    const int warp = tid >> 5, lane = tid & 31;
    const int wm = (warp >> 1) * 32, wn = (warp & 1) * 32;
    const int g4 = lane >> 2, l4 = lane & 3;

    const int lr  = tid >> 3;
    const int lcb = (tid & 7) * 8;

    const u16* AgP[4]; u32 adP[4];
    #pragma unroll
    for (int p = 0; p < 4; p++) {
        const int row = p * 32 + lr;
        AgP[p] = A + (size_t)row * lda + lcb;
        adP[p] = smem_u32(As) + (u32)((row * RP + (tid & 7) * 4) * 4);
    }
    const u16* WgP[2]; u32 bdP[2];
    #pragma unroll
    for (int p = 0; p < 2; p++) {
        const int row = p * 32 + lr;
        WgP[p] = W + (size_t)(bn + row) * ldw + lcb;
        bdP[p] = smem_u32(Bs) + (u32)((row * RP + (tid & 7) * 4) * 4);
    }

    const FragAddr f = frag_setup(As, Bs, wm, wn, lane);
    const int niter = K >> 6;

    #pragma unroll
    for (int s = 0; s < 2; s++) {
        if (s < niter) {
            const int k0 = s << 6;
            #pragma unroll
            for (int p = 0; p < 4; p++) cp16(adP[p] + s * A_ST4,  AgP[p] + k0);
            #pragma unroll
            for (int p = 0; p < 2; p++) cp16(bdP[p] + s * BL_ST4, WgP[p] + k0);
        }
        CP_COMMIT();
    }

    float acc[2][4][4];
    #pragma unroll
    for (int i = 0; i < 2; i++)
        #pragma unroll
        for (int j = 0; j < 4; j++)
            #pragma unroll
            for (int r = 0; r < 4; r++) acc[i][j][r] = 0.f;

    for (int it = 0; it < niter; it++) {
        CP_WAIT1();
        __syncthreads();
        const int nx = it + 2;
        if (nx < niter) {
            const int bufn = nx % 3;
            const int k0 = nx << 6;
            #pragma unroll
            for (int p = 0; p < 4; p++) cp16(adP[p] + bufn * A_ST4,  AgP[p] + k0);
            #pragma unroll
            for (int p = 0; p < 2; p++) cp16(bdP[p] + bufn * BL_ST4, WgP[p] + k0);
        }
        CP_COMMIT();
        const int buf = it % 3;
        mma_slab64(acc, f, (u32)buf * A_ST4, (u32)buf * BL_ST4);
    }

    #pragma unroll
    for (int mt = 0; mt < 2; mt++) {
        const int r0 = wm + mt * 16 + g4;
        const int r1 = r0 + 8;
        #pragma unroll
        for (int nt = 0; nt < 4; nt++) {
            const int n = bn + wn + nt * 8 + l4 * 2;
            #pragma unroll
            for (int c = 0; c < 2; c++) {
                const int nn = n + c;
                float add = bias ? bias[nn] : 0.0f;
                float v0 = acc[mt][nt][c]     + add;
                float v1 = acc[mt][nt][c + 2] + add;
                if (D) {
                    v0 += D[(size_t)r0 * ldc + nn];
                    v1 += D[(size_t)r1 * ldc + nn];
                }
                C[(size_t)r0 * ldc + nn] = v0;
                C[(size_t)r1 * ldc + nn] = v1;
            }
        }
    }
}

// ---------------- persistent loop kernel ----------------------------------------
__global__ void __launch_bounds__(256)
loop_kernel(const float* __restrict__ Wa, const float* __restrict__ ba,
            const float* __restrict__ bhh1, const float* __restrict__ bhh2,
            int nsteps)
{
    extern __shared__ u32 dsm[];
    u32* sA = dsm;
    u32* sB = dsm + 3 * A_ST;

    const int tid = threadIdx.x;
    const int blk = blockIdx.x;
    unsigned bt = 0;

    for (int t = 0; t < nsteps; t++) {
        // ---- phase 1: multiA (gi1_h2 +const, gh1, gh2): 144 tiles ----
        if (blk < 144) {
            const int d = blk / 48, bn = (blk % 48) * 64;
            const u16 *A, *W; float* C;
            const float *bias = nullptr, *Dp = nullptr;
            int ldw;
            if (d == 0) {
                A = g_Xb16 + (size_t)t * B_ * HID_; W = g_Wih1_b; ldw = 4096;
                C = g_gp; Dp = g_gi1ctot + (size_t)t * B_ * H3_;
            } else if (d == 1) {
                A = g_h1b16; W = g_Whh1_b; ldw = HID_; C = g_gq; bias = bhh1;
            } else {
                A = g_Xb16 + (size_t)t * B_ * HID_; W = g_Whh2_b; ldw = HID_;
                C = g_gs; bias = bhh2;
            }
            gemm_tile(A, HID_, W, ldw, C, H3_, bias, Dp, bn, HID_, sA, sB);
        }
        bt += 148; grid_bar(bt);

        // ---- phase 2: gru1 elementwise ----
        for (int idx = blk * 256 + tid; idx < B_ * HID_; idx += gridDim.x * 256) {
            const int b = idx >> 10, j = idx & 1023;
            const size_t o = (size_t)b * H3_;
            float ir  = g_gp[o + j];
            float iz  = g_gp[o + j + 1024];
            float in_ = g_gp[o + j + 2048];
            float hr  = g_gq[o + j];
            float hz  = g_gq[o + j + 1024];
            float hn  = g_gq[o + j + 2048];
            float r = 1.f / (1.f + expf(-(ir + hr)));
            float z = 1.f / (1.f + expf(-(iz + hz)));
            float n = tanhf(in_ + r * hn);
            float hnew = (1.f - z) * n + z * g_h1[idx];
            g_h1[idx] = hnew;
            __nv_bfloat16 hb = __float2bfloat16(hnew);
            g_h1b16[idx] = *(u16*)&hb;
        }
        bt += 148; grid_bar(bt);

        // ---- phase 3: multiB split-K x2 (q: 32 tiles, gi2h: 96 tiles) ----
        if (blk < 128) {
            if (blk < 32) {
                const int s = blk >> 4;
                const int bn = (blk & 15) * 64;
                gemm_tile(g_h1b16 + s * 512, HID_, g_Wqf_b + s * 512, HID_,
                          s ? g_q2 : g_q, HID_,
                          s ? nullptr : g_bqf, nullptr, bn, 512, sA, sB);
            } else {
                const int j = blk - 32;
                const int s = j / 48;
                const int bn = (j % 48) * 64;
                gemm_tile(g_h1b16 + s * 512, HID_, g_Wih2f_b + s * 512, HID_,
                          s ? g_gi2h2 : g_gi2h, H3_,
                          s ? nullptr : g_bih2f, nullptr, bn, 512, sA, sB);
            }
        }
        bt += 148; grid_bar(bt);

        // ---- phase 4: attention + gi2 assembly + GRU2 (128 rows) ----
        if (blk < B_) {
            const int b = blk;
            float* gi2s = (float*)sA;
            float* qa   = (float*)sB;
            float* lg   = (float*)sB + 1024;

            for (int h = tid; h < HID_; h += 256)
                qa[h] = fmaxf(g_q[b * HID_ + h] + g_q2[b * HID_ + h], 0.f) * Wa[h];
            __syncthreads();

            const int warp = tid >> 5, lane = tid & 31;
            for (int o = warp; o < NOBJ_; o += 8) {
                const float* vp = g_vproj + ((size_t)b * NOBJ_ + o) * HID_;
                float s = 0.f;
                for (int h = lane; h < HID_; h += 32) s += qa[h] * vp[h];
                #pragma unroll
                for (int off = 16; off; off >>= 1)
                    s += __shfl_xor_sync(0xffffffffu, s, off);
                if (lane == 0) lg[o] = s + ba[0];
            }
            __syncthreads();

            if (tid == 0) {
                float mx = -1e30f;
                for (int o = 0; o < NOBJ_; o++) mx = fmaxf(mx, lg[o]);
                float sum = 0.f;
                for (int o = 0; o < NOBJ_; o++) {
                    float e = expf(lg[o] - mx); lg[o] = e; sum += e;
                }
                float inv = 1.f / sum;
                for (int o = 0; o < NOBJ_; o++) lg[o] *= inv;
            }
            __syncthreads();

            if (tid < NOBJ_)
                g_alpha[((size_t)b * TSTEPS_ + t) * NOBJ_ + tid] = lg[tid];

            const __nv_bfloat162* vw =
                (const __nv_bfloat162*)(g_vW2b + (size_t)b * NOBJ_ * H3_);
            for (int c2 = tid * 2; c2 < H3_; c2 += 512) {
                float s0 = 0.f, s1 = 0.f;
                #pragma unroll
                for (int o = 0; o < NOBJ_; o++) {
                    __nv_bfloat162 w = vw[((size_t)o * H3_ + c2) >> 1];
                    s0 += lg[o] * __bfloat162float(__low2bfloat16(w));
                    s1 += lg[o] * __bfloat162float(__high2bfloat16(w));
                }
                gi2s[c2]     = s0 + g_gi2h[b * H3_ + c2]     + g_gi2h2[b * H3_ + c2];
                gi2s[c2 + 1] = s1 + g_gi2h[b * H3_ + c2 + 1] + g_gi2h2[b * H3_ + c2 + 1];
            }
            __syncthreads();

            for (int j = tid; j < HID_; j += 256) {
                const size_t o = (size_t)b * H3_;
                float r = 1.f / (1.f + expf(-(gi2s[j]        + g_gs[o + j])));
                float z = 1.f / (1.f + expf(-(gi2s[j + 1024] + g_gs[o + j + 1024])));
                float n = tanhf(gi2s[j + 2048] + r * g_gs[o + j + 2048]);
                float hold = g_Xbig[(size_t)t * B_ * XW_ + b * XW_ + j];
                float hnew = (1.f - z) * n + z * hold;
                g_Xbig[(size_t)(t + 1) * B_ * XW_ + b * XW_ + j] = hnew;
                __nv_bfloat16 hb = __float2bfloat16(hnew);
                g_Xb16[(size_t)(t + 1) * B_ * HID_ + b * HID_ + j] = *(u16*)&hb;
                g_histb16[(size_t)t * B_ * HID_ + b * HID_ + j]    = *(u16*)&hb;
            }
        }
        bt += 148; grid_bar(bt);
    }
}

// ---------------- standalone bf16-A GEMM: 128x128, BK=64, 3-stage --------------
struct GD {
    const u16* A; const u16* W; float* C;
    const float* bias; const float* D;
    const int* rowmap; const int* rowcnt;
    int lda, ldw, ldc, N, K, M, flags;
};
template<int ND> struct GParams { GD d[ND]; };

template<int ND>
__global__ void __launch_bounds__(256)
mma_multi(GParams<ND> p)
{
    const GD g = p.d[blockIdx.y];
    const int bn = blockIdx.x * 128;
    if (bn >= g.N) return;
    const int mbase = blockIdx.z * 128;

    extern __shared__ u32 dsm[];
    u32* As = dsm;
    u32* Bs = dsm + 3 * A_ST;
    __shared__ int rmap[128];

    const int tid = threadIdx.x;

    if (g.rowmap) {
        const int cnt = *g.rowcnt;
        if (mbase >= cnt) return;
        if (tid < 128)
            rmap[tid] = (mbase + tid < cnt) ? g.rowmap[mbase + tid] : -1;
        __syncthreads();
    } else {
        if (mbase >= g.M) return;
    }

    const int warp = tid >> 5, lane = tid & 31;
    const int wm = (warp >> 1) * 32;
    const int wn = (warp & 1) * 64;
    const int g4 = lane >> 2;
    const int l4 = lane & 3;

    const int lr  = tid >> 3;
    const int lcb = (tid & 7) * 8;

    const u16* AgP[4]; u32 adP[4];
    #pragma unroll
    for (int pp = 0; pp < 4; pp++) {
        const int row = pp * 32 + lr;
        int arow;
        if (g.rowmap) { int rm = rmap[row]; arow = rm < 0 ? 0 : rm; }
        else arow = mbase + row;
        AgP[pp] = g.A + (size_t)arow * g.lda + lcb;
        adP[pp] = smem_u32(As) + (u32)((row * RP + (tid & 7) * 4) * 4);
    }
    const u16* WgP[4]; u32 bdP[4]; u32 bszP[4];
    #pragma unroll
    for (int pp = 0; pp < 4; pp++) {
        const int row = pp * 32 + lr;
        const bool ok = (bn + row) < g.N;
        const int wrow = ok ? (bn + row) : (g.N - 1);
        WgP[pp]  = g.W + (size_t)wrow * g.ldw + lcb;
        bdP[pp]  = smem_u32(Bs) + (u32)((row * RP + (tid & 7) * 4) * 4);
        bszP[pp] = ok ? 16u : 0u;
    }

    u32 fa[2], fb[4];
    {
        const u32 AsB = smem_u32(As);
        const u32 BsB = smem_u32(Bs);
        const int rowA = wm + (lane & 7) + ((lane >> 3) & 1) * 8;
        const int kwA  = ((lane >> 4) & 1) * 4;
        const int rowB = wn + (lane & 7) + ((lane >> 4) & 1) * 8;
        const int kwB  = ((lane >> 3) & 1) * 4;
        #pragma unroll
        for (int mt = 0; mt < 2; mt++)
            fa[mt] = AsB + (u32)(((rowA + mt * 16) * RP + kwA) * 4);
        #pragma unroll
        for (int np = 0; np < 4; np++)
            fb[np] = BsB + (u32)(((rowB + np * 16) * RP + kwB) * 4);
    }

    const int niter = g.K >> 6;

    #pragma unroll
    for (int s = 0; s < 2; s++) {
        if (s < niter) {
            const int k0 = s << 6;
            #pragma unroll
            for (int pp = 0; pp < 4; pp++) cp16(adP[pp] + s * A_ST4, AgP[pp] + k0);
            #pragma unroll
            for (int pp = 0; pp < 4; pp++)
                cp16z(bdP[pp] + s * B2_ST4, WgP[pp] + k0, bszP[pp]);
        }
        CP_COMMIT();
    }

    float acc[2][8][4];
    #pragma unroll
    for (int i = 0; i < 2; i++)
        #pragma unroll
        for (int j = 0; j < 8; j++)
            #pragma unroll
            for (int r = 0; r < 4; r++) acc[i][j][r] = 0.f;

    for (int it = 0; it < niter; it++) {
        CP_WAIT1();
        __syncthreads();
        const int nx = it + 2;
        if (nx < niter) {
            const int bufn = nx % 3;
            const int k0 = nx << 6;
            #pragma unroll
            for (int pp = 0; pp < 4; pp++) cp16(adP[pp] + bufn * A_ST4, AgP[pp] + k0);
            #pragma unroll
            for (int pp = 0; pp < 4; pp++)
                cp16z(bdP[pp] + bufn * B2_ST4, WgP[pp] + k0, bszP[pp]);
        }
        CP_COMMIT();
        const u32 bufA = (u32)(it % 3) * A_ST4;
        const u32 bufB = (u32)(it % 3) * B2_ST4;

        #pragma unroll
        for (int ks = 0; ks < 4; ks++) {
            const u32 ko = ks * 32;
            u32 a0[4], a1[4], b[4][4];
            ldsm4(a0[0], a0[1], a0[2], a0[3], fa[0] + bufA + ko);
            ldsm4(a1[0], a1[1], a1[2], a1[3], fa[1] + bufA + ko);
            #pragma unroll
            for (int np = 0; np < 4; np++)
                ldsm4(b[np][0], b[np][1], b[np][2], b[np][3], fb[np] + bufB + ko);
            #pragma unroll
            for (int np = 0; np < 4; np++) {
                mma16(acc[0][2 * np],     a0, b[np][0], b[np][1]);
                mma16(acc[1][2 * np],     a1, b[np][0], b[np][1]);
                mma16(acc[0][2 * np + 1], a0, b[np][2], b[np][3]);
                mma16(acc[1][2 * np + 1], a1, b[np][2], b[np][3]);
            }
        }
    }

    #pragma unroll
    for (int mt = 0; mt < 2; mt++) {
        const int ml = wm + mt * 16 + g4;
        int r0, r1; bool ok0 = true, ok1 = true;
        if (g.rowmap) {
            r0 = rmap[ml]; r1 = rmap[ml + 8];
            ok0 = r0 >= 0; ok1 = r1 >= 0;
            if (r0 < 0) r0 = 0; if (r1 < 0) r1 = 0;
        } else {
            r0 = mbase + ml; r1 = r0 + 8;
            ok0 = r0 < g.M; ok1 = r1 < g.M;
            if (!ok0) r0 = 0; if (!ok1) r1 = 0;
        }
        const int dr0 = (g.flags & FLAG_DMOD) ? (r0 & (B_ - 1)) : r0;
        const int dr1 = (g.flags & FLAG_DMOD) ? (r1 & (B_ - 1)) : r1;
        #pragma unroll
        for (int nt = 0; nt < 8; nt++) {
            const int n = bn + wn + nt * 8 + l4 * 2;
            #pragma unroll
            for (int c = 0; c < 2; c++) {
                const int nn = n + c;
                if (nn >= g.N) continue;
                float add = g.bias ? g.bias[nn] : 0.0f;
                float v0 = acc[mt][nt][c]     + add;
                float v1 = acc[mt][nt][c + 2] + add;
                if (g.D) {
                    v0 += g.D[(size_t)dr0 * g.ldc + nn];
                    v1 += g.D[(size_t)dr1 * g.ldc + nn];
                }
                if (g.flags & FLAG_RELU) { v0 = fmaxf(v0, 0.f); v1 = fmaxf(v1, 0.f); }
                if (g.flags & FLAG_BF16) {
                    __nv_bfloat16* Cb = (__nv_bfloat16*)g.C;
                    if (ok0) Cb[(size_t)r0 * g.ldc + nn] = __float2bfloat16(v0);
                    if (ok1) Cb[(size_t)r1 * g.ldc + nn] = __float2bfloat16(v1);
                } else {
                    if (ok0) g.C[(size_t)r0 * g.ldc + nn] = v0;
                    if (ok1) g.C[(size_t)r1 * g.ldc + nn] = v1;
                }
            }
        }
    }
}

// ---------------- packed vectorized f32->bf16 conversion ------------------------
template<int ND> struct CvtPack {
    const float* src[ND];
    u16* dst[ND];
    int cum[ND + 1];
};

template<int ND>
__global__ void __launch_bounds__(256)
cvt_pack(CvtPack<ND> p)
{
    const int blk = blockIdx.x;
    int k = 0;
    #pragma unroll
    for (int i = 0; i < ND - 1; i++)
        if (blk >= p.cum[i + 1]) k = i + 1;
    const float* src = p.src[k];
    u16* dst = p.dst[k];
    const int base = (blk - p.cum[k]) * 2048 + threadIdx.x * 8;
    float4 a = *(const float4*)(src + base);
    float4 b = *(const float4*)(src + base + 4);
    uint4 o;
    o.x = pack_bf2(a.x, a.y);
    o.y = pack_bf2(a.z, a.w);
    o.z = pack_bf2(b.x, b.y);
    o.w = pack_bf2(b.z, b.w);
    *(uint4*)(dst + base) = o;
}

// ---------------- weight prep + small kernels -----------------------------------
__global__ void transpose_wfc1_kernel(const float* __restrict__ Wfc1) {
    __shared__ float tile[32][33];
    int x  = blockIdx.x * 32 + threadIdx.x;
    int y0 = blockIdx.y * 32;
    for (int i = threadIdx.y; i < 32; i += 8)
        tile[i][threadIdx.x] = Wfc1[(size_t)(y0 + i) * HID_ + x];
    __syncthreads();
    int xo  = blockIdx.y * 32 + threadIdx.x;
    int yo0 = blockIdx.x * 32;
    for (int i = threadIdx.y; i < 32; i += 8)
        g_WfcT[(size_t)(yo0 + i) * HID_ + xo] = tile[threadIdx.x][i];
}

__global__ void bqf_kernel(const float* __restrict__ Wq,
                           const float* __restrict__ bq,
                           const float* __restrict__ bfc1) {
    int j = blockIdx.x, tid = threadIdx.x;
    __shared__ float red[256];
    float s = 0.f;
    for (int n = tid; n < HID_; n += 256) s += Wq[(size_t)j * HID_ + n] * bfc1[n];
    red[tid] = s; __syncthreads();
    for (int st = 128; st; st >>= 1) {
        if (tid < st) red[tid] += red[tid + st];
        __syncthreads();
    }
    if (tid == 0) g_bqf[j] = bq[j] + red[0];
}

__global__ void bih2f_kernel(const float* __restrict__ Wih2,
                             const float* __restrict__ bih2,
                             const float* __restrict__ bfc1) {
    int j = blockIdx.x, tid = threadIdx.x;
    __shared__ float red[256];
    float s = 0.f;
    for (int n = tid; n < HID_; n += 256)
        s += Wih2[(size_t)j * H3_ + 2048 + n] * bfc1[n];
    red[tid] = s; __syncthreads();
    for (int st = 128; st; st >>= 1) {
        if (tid < st) red[tid] += red[tid + st];
        __syncthreads();
    }
    if (tid == 0) g_bih2f[j] = bih2[j] + red[0];
}

__global__ void build_rows_kernel(const int* __restrict__ cap_len) {
    int lane = threadIdx.x;
    int total = 0;
    for (int t = 0; t < TSTEPS_; t++) {
        for (int gb = 0; gb < 4; gb++) {
            int b = gb * 32 + lane;
            bool act = t < cap_len[b] - 1;
            unsigned m = __ballot_sync(0xffffffffu, act);
            int pos = total + __popc(m & ((1u << lane) - 1u));
            if (act) g_rowmap[pos] = t * B_ + b;
            total += __popc(m);
        }
    }
    if (lane == 0) g_rowcnt[0] = total;
}

__global__ void zero_init_kernel() {
    int i = blockIdx.x * 256 + threadIdx.x;
    g_h1[i] = 0.f;
    g_h1b16[i] = 0;
    g_Xb16[i] = 0;
    int b = i >> 10, j = i & 1023;
    g_Xbig[b * XW_ + j] = 0.f;
    if (i == 0) g_bar_cnt = 0u;
}

__global__ void sortid_kernel(const int* __restrict__ cap_len) {
    __shared__ int len[B_];
    int i = threadIdx.x;
    len[i] = cap_len[i];
    __syncthreads();
    int my = len[i], rank = 0;
    for (int j = 0; j < B_; j++)
        rank += (len[j] > my) || (len[j] == my && j < i);
    g_sortid[rank] = i;
}

__global__ void vmean_kernel(const float* __restrict__ v) {
    int idx = blockIdx.x * 256 + threadIdx.x;
    int b = idx >> 11, d = idx & 2047;
    float s = 0.f;
    #pragma unroll 4
    for (int o = 0; o < NOBJ_; o++)
        s += v[((size_t)b * NOBJ_ + o) * VDIM_ + d];
    __nv_bfloat16 m = __float2bfloat16(s * (1.0f / NOBJ_));
    g_vmeanb[idx] = *(u16*)&m;
}

__global__ void cap_all_kernel(const int* __restrict__ caption,
                               const float* __restrict__ emb) {
    int idx = blockIdx.x * 256 + threadIdx.x;
    int t = idx / (B_ * EMBED_);
    int r = idx % (B_ * EMBED_);
    int b = r >> 10, e = r & 1023;
    int tok = caption[b * MAXLEN_ + t];
    __nv_bfloat16 c = __float2bfloat16(emb[(size_t)tok * EMBED_ + e]);
    g_capb16[idx] = *(u16*)&c;
}

__global__ void __launch_bounds__(256)
final_predict_kernel(const int* __restrict__ cap_len, float* __restrict__ out) {
    const int t = blockIdx.x, b = blockIdx.y, tid = threadIdx.x;
    float* dst = out + ((size_t)b * MAXLEN_ + t) * NTOK_;
    const int declen = cap_len[b] - 1;
    if (t >= declen || t >= TSTEPS_) {
        const float u = 1.0f / (float)NTOK_;
        for (int i = tid; i < NTOK_; i += 256) dst[i] = u;
        return;
    }
    extern __shared__ float es[];
    const float* src = g_logits + ((size_t)t * B_ + b) * NTOK_;
    __shared__ float red[256];
    float mx = -1e30f;
    for (int i = tid; i < NTOK_; i += 256) mx = fmaxf(mx, src[i]);
    red[tid] = mx; __syncthreads();
    for (int s = 128; s; s >>= 1) {
        if (tid < s) red[tid] = fmaxf(red[tid], red[tid + s]);
        __syncthreads();
    }
    mx = red[0]; __syncthreads();
    float sum = 0.f;
    for (int i = tid; i < NTOK_; i += 256) {
        float e = expf(src[i] - mx);
        es[i] = e;
        sum += e;
    }
    red[tid] = sum; __syncthreads();
    for (int s = 128; s; s >>= 1) {
        if (tid < s) red[tid] += red[tid + s];
        __syncthreads();
    }
    const float inv = 1.f / red[0];
    for (int i = tid; i < NTOK_; i += 256) dst[i] = es[i] * inv;
}

__global__ void sc_out_kernel(const int* __restrict__ caption, float* __restrict__ dst) {
    int idx = blockIdx.x * 256 + threadIdx.x;
    if (idx >= B_ * TSTEPS_) return;
    int k = idx / TSTEPS_, j = idx % TSTEPS_;
    dst[idx] = (float)caption[g_sortid[k] * MAXLEN_ + j + 1];
}

__global__ void alpha_out_kernel(const int* __restrict__ cap_len, float* __restrict__ dst) {
    int idx = blockIdx.x * 256 + threadIdx.x;
    if (idx >= B_ * MAXLEN_ * NOBJ_) return;
    int b = idx / (MAXLEN_ * NOBJ_);
    int r = idx % (MAXLEN_ * NOBJ_);
    int t = r / NOBJ_, o = r % NOBJ_;
    float val = 0.f;
    if (t < TSTEPS_ && t < cap_len[b] - 1)
        val = g_alpha[((size_t)b * TSTEPS_ + t) * NOBJ_ + o];
    dst[idx] = val;
}

// ---------------- host side -------------------------------------------------------
template<typename T>
static inline void* symaddr(T& sym) {
    void* p = nullptr;
    cudaGetSymbolAddress(&p, sym);
    return p;
}

static inline GD mk(const u16* A, int lda, const u16* W, int ldw,
                    float* C, int ldc, const float* bias, const float* D,
                    int N, int K, int M, int flags,
                    const int* rowmap = nullptr, const int* rowcnt = nullptr) {
    GD g; g.A = A; g.W = W; g.C = C; g.bias = bias; g.D = D;
    g.rowmap = rowmap; g.rowcnt = rowcnt;
    g.lda = lda; g.ldw = ldw; g.ldc = ldc; g.N = N; g.K = K; g.M = M;
    g.flags = flags;
    return g;
}

extern "C" void kernel_launch(void* const* d_in, const int* in_sizes, int n_in,
                              void* d_out, int out_size) {
    (void)in_sizes; (void)n_in; (void)out_size;
    const float* v       = (const float*)d_in[0];
    const int*   caption = (const int*)  d_in[1];
    const int*   cap_len = (const int*)  d_in[2];
    const float* emb     = (const float*)d_in[3];
    const float* Wih1    = (const float*)d_in[4];
    const float* Whh1    = (const float*)d_in[5];
    const float* bih1    = (const float*)d_in[6];
    const float* bhh1    = (const float*)d_in[7];
    const float* Wih2    = (const float*)d_in[8];
    const float* Whh2    = (const float*)d_in[9];
    const float* bih2    = (const float*)d_in[10];
    const float* bhh2    = (const float*)d_in[11];
    const float* Wfc1    = (const float*)d_in[12];
    const float* bfc1    = (const float*)d_in[13];
    const float* Wfc2    = (const float*)d_in[14];
    const float* bfc2    = (const float*)d_in[15];
    const float* Wv      = (const float*)d_in[16];
    const float* bv      = (const float*)d_in[17];
    const float* Wq      = (const float*)d_in[18];
    const float* bq      = (const float*)d_in[19];
    const float* Wa      = (const float*)d_in[20];
    const float* ba      = (const float*)d_in[21];
    float* out = (float*)d_out;

    float* logits  = (float*)symaddr(g_logits);
    float* gi1ctot = (float*)symaddr(g_gi1ctot);
    float* gi1mean = (float*)symaddr(g_gi1mean);
    float* vproj   = (float*)symaddr(g_vproj);
    float* WfcT    = (float*)symaddr(g_WfcT);
    float* WqfF    = (float*)symaddr(g_WqfF);
    float* Wih2fF  = (float*)symaddr(g_Wih2fF);
    int*   rowmap  = (int*)  symaddr(g_rowmap);
    int*   rowcnt  = (int*)  symaddr(g_rowcnt);

    u16* vb16    = (u16*)symaddr(g_vb16);
    u16* vmeanb  = (u16*)symaddr(g_vmeanb);
    u16* capb16  = (u16*)symaddr(g_capb16);
    u16* histb16 = (u16*)symaddr(g_histb16);
    u16* Wq_b16  = (u16*)symaddr(g_Wq_b16);
    u16* Wih1_b  = (u16*)symaddr(g_Wih1_b);
    u16* Whh1_b  = (u16*)symaddr(g_Whh1_b);
    u16* Whh2_b  = (u16*)symaddr(g_Whh2_b);
    u16* Wih2_b  = (u16*)symaddr(g_Wih2_b);
    u16* Wqf_b   = (u16*)symaddr(g_Wqf_b);
    u16* Wih2f_b = (u16*)symaddr(g_Wih2f_b);
    u16* WfcT_b  = (u16*)symaddr(g_WfcT_b);
    u16* Wv_b    = (u16*)symaddr(g_Wv_b);
    u16* Wfc2_b  = (u16*)symaddr(g_Wfc2_b);
    u16* vW2b    = (u16*)symaddr(g_vW2b);

    cudaFuncSetAttribute(final_predict_kernel,
                         cudaFuncAttributeMaxDynamicSharedMemorySize, NTOK_ * 4);
    cudaFuncSetAttribute(mma_multi<1>,
                         cudaFuncAttributeMaxDynamicSharedMemorySize, MM_SMEM);
    cudaFuncSetAttribute(mma_multi<5>,
                         cudaFuncAttributeMaxDynamicSharedMemorySize, MM_SMEM);
    cudaFuncSetAttribute(loop_kernel,
                         cudaFuncAttributeMaxDynamicSharedMemorySize, LOOP_SMEM);

    // ---- prologue: data prep ----
    zero_init_kernel<<<512, 256>>>();
    sortid_kernel<<<1, 128>>>(cap_len);
    vmean_kernel<<<(B_ * VDIM_) / 256, 256>>>(v);
    cap_all_kernel<<<(TSTEPS_ * B_ * EMBED_) / 256, 256>>>(caption, emb);
    build_rows_kernel<<<1, 32>>>(cap_len);
    transpose_wfc1_kernel<<<dim3(32, 32), dim3(32, 8)>>>(Wfc1);
    bqf_kernel<<<HID_, 256>>>(Wq, bq, bfc1);
    bih2f_kernel<<<H3_, 256>>>(Wih2, bih2, bfc1);

    // ---- ONE packed vectorized conversion for all pre-GEMM arrays ----
    {
        CvtPack<9> cp;
        const float* srcs[9] = { Wih1, Whh1, Whh2, Wih2, Wv, Wfc2, Wq, v, WfcT };
        u16* dsts[9] = { Wih1_b, Whh1_b, Whh2_b, Wih2_b, Wv_b, Wfc2_b,
                         Wq_b16, vb16, WfcT_b };
        const int ns[9] = { H3_ * 4096, H3_ * HID_, H3_ * HID_, H3_ * H3_,
                            HID_ * VDIM_, NTOK_ * HID_, HID_ * HID_,
                            B_ * NOBJ_ * VDIM_, HID_ * HID_ };
        int cum = 0;
        for (int i = 0; i < 9; i++) {
            cp.src[i] = srcs[i]; cp.dst[i] = dsts[i];
            cp.cum[i] = cum; cum += ns[i] / 2048;
        }
        cp.cum[9] = cum;
        cvt_pack<9><<<cum, 256>>>(cp);
    }

    // ---- 5 independent prologue GEMMs in one launch ----
    {
        GParams<5> p;
        p.d[0] = mk(vb16, VDIM_, Wv_b, VDIM_, vproj, HID_,
                    bv, nullptr, HID_, VDIM_, B_ * NOBJ_, FLAG_RELU);
        p.d[1] = mk(vb16, VDIM_, Wih2_b, H3_, (float*)vW2b, H3_,
                    nullptr, nullptr, H3_, VDIM_, B_ * NOBJ_, FLAG_BF16);
        p.d[2] = mk(Wq_b16, HID_, WfcT_b, HID_, WqfF, HID_,
                    nullptr, nullptr, HID_, HID_, HID_, 0);
        p.d[3] = mk(Wih2_b + 2048, H3_, WfcT_b, HID_, Wih2fF, HID_,
                    nullptr, nullptr, HID_, HID_, H3_, 0);
        p.d[4] = mk(vmeanb, VDIM_, Wih1_b + 1024, 4096, gi1mean, H3_,
                    bih1, nullptr, H3_, VDIM_, B_, 0);
        mma_multi<5><<<dim3(24, 5, 36), 256, MM_SMEM>>>(p);
    }
    // ---- gi1ctot GEMM (depends on gi1mean -> separate launch) ----
    {
        GParams<1> p;
        p.d[0] = mk(capb16, EMBED_, Wih1_b + 3072, 4096, gi1ctot, H3_,
                    nullptr, gi1mean, H3_, 1024, TSTEPS_ * B_, FLAG_DMOD,
                    rowmap, rowcnt);
        mma_multi<1><<<dim3(24, 1, TSTEPS_), 256, MM_SMEM>>>(p);
    }
    // ---- post-GEMM conversions (packed) ----
    {
        CvtPack<2> cp;
        cp.src[0] = WqfF;   cp.dst[0] = Wqf_b;
        cp.src[1] = Wih2fF; cp.dst[1] = Wih2f_b;
        cp.cum[0] = 0;
        cp.cum[1] = (HID_ * HID_) / 2048;
        cp.cum[2] = cp.cum[1] + (H3_ * HID_) / 2048;
        cvt_pack<2><<<cp.cum[2], 256>>>(cp);
    }

    // ---- full 19-step loop in ONE persistent launch ----
    loop_kernel<<<148, 256, LOOP_SMEM>>>(Wa, ba, bhh1, bhh2, TSTEPS_);

    // ---- deferred row-compacted logits GEMM ----
    {
        GParams<1> p;
        p.d[0] = mk(histb16, HID_, Wfc2_b, HID_, logits, NTOK_,
                    bfc2, nullptr, NTOK_, HID_, TSTEPS_ * B_, 0,
                    rowmap, rowcnt);
        mma_multi<1><<<dim3(118, 1, TSTEPS_), 256, MM_SMEM>>>(p);
    }

    // ---- epilogue ----
    dim3 gpd(MAXLEN_, B_);
    final_predict_kernel<<<gpd, 256, NTOK_ * 4>>>(cap_len, out);
    sc_out_kernel<<<(B_ * TSTEPS_ + 255) / 256, 256>>>(caption,
        out + (size_t)B_ * MAXLEN_ * NTOK_);
    alpha_out_kernel<<<(B_ * MAXLEN_ * NOBJ_ + 255) / 256, 256>>>(cap_len,
        out + (size_t)B_ * MAXLEN_ * NTOK_ + (size_t)B_ * TSTEPS_);
}